// round 5
// baseline (speedup 1.0000x reference)
#include <cuda_runtime.h>
#include <cuda_bf16.h>
#include <cstdint>

#define Bz    2
#define Sq    2048
#define DIM   1024
#define Hn    16
#define DHd   64
#define INNER 1024
#define TOK   4096

// ---------------------------------------------------------------------------
// Scratch (device globals). Fragment arrays are uint32 (packed bf16x2).
// ---------------------------------------------------------------------------
__device__ uint32_t g_xn_h[TOK*DIM/2],      g_xn_l[TOK*DIM/2];
__device__ uint32_t g_Wqkv_h[DIM*3*INNER/2], g_Wqkv_l[DIM*3*INNER/2];
__device__ uint32_t g_Wo_h[INNER*DIM/2],    g_Wo_l[INNER*DIM/2];
__device__ float    g_qkv[TOK*3*INNER];
__device__ uint32_t g_qf_h[TOK*INNER/2],    g_qf_l[TOK*INNER/2];
__device__ uint32_t g_kf_h[TOK*INNER/2],    g_kf_l[TOK*INNER/2];
__device__ uint32_t g_vf_h[TOK*INNER/2],    g_vf_l[TOK*INNER/2];
__device__ uint32_t g_ao_h[TOK*INNER/2],    g_ao_l[TOK*INNER/2];

// ---------------------------------------------------------------------------
// Helpers
// ---------------------------------------------------------------------------
__device__ __forceinline__ uint32_t smem_u32(const void* p) {
    uint32_t a;
    asm("{ .reg .u64 t; cvta.to.shared.u64 t, %1; cvt.u32.u64 %0, t; }" : "=r"(a) : "l"(p));
    return a;
}
__device__ __forceinline__ uint32_t pkbf(float a, float b) {
    return (uint32_t)__bfloat16_as_ushort(__float2bfloat16_rn(a)) |
           ((uint32_t)__bfloat16_as_ushort(__float2bfloat16_rn(b)) << 16);
}
__device__ __forceinline__ void splitbf(float a, float b, uint32_t& hi, uint32_t& lo) {
    __nv_bfloat16 ha = __float2bfloat16_rn(a), hb = __float2bfloat16_rn(b);
    hi = (uint32_t)__bfloat16_as_ushort(ha) | ((uint32_t)__bfloat16_as_ushort(hb) << 16);
    lo = pkbf(a - __bfloat162float(ha), b - __bfloat162float(hb));
}
__device__ __forceinline__ void mma_bf(float* c, const uint32_t* a, const uint32_t* b) {
    asm volatile(
        "mma.sync.aligned.m16n8k16.row.col.f32.bf16.bf16.f32 "
        "{%0,%1,%2,%3}, {%4,%5,%6,%7}, {%8,%9}, {%0,%1,%2,%3};"
        : "+f"(c[0]), "+f"(c[1]), "+f"(c[2]), "+f"(c[3])
        : "r"(a[0]), "r"(a[1]), "r"(a[2]), "r"(a[3]), "r"(b[0]), "r"(b[1]));
}
__device__ __forceinline__ void cpa16(uint32_t saddr, const void* gptr) {
    asm volatile("cp.async.cg.shared.global [%0], [%1], 16;" :: "r"(saddr), "l"(gptr) : "memory");
}
__device__ __forceinline__ void cp_commit() { asm volatile("cp.async.commit_group;" ::: "memory"); }
template <int N> __device__ __forceinline__ void cp_wait() {
    asm volatile("cp.async.wait_group %0;" :: "n"(N) : "memory");
}

// ---------------------------------------------------------------------------
// 1) LayerNorm -> A-fragment-major bf16 hi/lo
// ---------------------------------------------------------------------------
__global__ void __launch_bounds__(256) ln_kernel(const float* __restrict__ x,
                                                 const float* __restrict__ w,
                                                 const float* __restrict__ bias,
                                                 uint32_t* __restrict__ xh,
                                                 uint32_t* __restrict__ xl) {
    const int row = blockIdx.x;
    const float* xr = x + (size_t)row * DIM;
    float2 v[2];
    v[0] = *(const float2*)(xr + 2 * threadIdx.x);
    v[1] = *(const float2*)(xr + 2 * (threadIdx.x + 256));
    float s  = v[0].x + v[0].y + v[1].x + v[1].y;
    float sq = v[0].x * v[0].x + v[0].y * v[0].y + v[1].x * v[1].x + v[1].y * v[1].y;
#pragma unroll
    for (int off = 16; off; off >>= 1) {
        s  += __shfl_xor_sync(0xffffffffu, s, off);
        sq += __shfl_xor_sync(0xffffffffu, sq, off);
    }
    __shared__ float red[2][8];
    const int warp = threadIdx.x >> 5, lane = threadIdx.x & 31;
    if (lane == 0) { red[0][warp] = s; red[1][warp] = sq; }
    __syncthreads();
    float ts = 0.f, tq2 = 0.f;
#pragma unroll
    for (int i = 0; i < 8; i++) { ts += red[0][i]; tq2 += red[1][i]; }
    const float mean = ts * (1.0f / DIM);
    const float var  = tq2 * (1.0f / DIM) - mean * mean;
    const float rstd = rsqrtf(var + 1e-5f);
    const int mt = row >> 4, mr = row & 15, g = mr & 7, hih = mr >> 3;
#pragma unroll
    for (int i = 0; i < 2; i++) {
        const int p = threadIdx.x + i * 256;
        const float2 wv = *(const float2*)(w + 2 * p);
        const float2 bv = *(const float2*)(bias + 2 * p);
        const float y0 = wv.x * (v[i].x - mean) * rstd + bv.x;
        const float y1 = wv.y * (v[i].y - mean) * rstd + bv.y;
        const int ks = p >> 3, c = p & 7, tq = c & 3, ch = c >> 2;
        const size_t idx = ((size_t)(mt * 64 + ks)) * 128 + (g * 4 + tq) * 4 + hih + 2 * ch;
        uint32_t hi, lo;
        splitbf(y0, y1, hi, lo);
        xh[idx] = hi; xl[idx] = lo;
    }
}

// ---------------------------------------------------------------------------
// 1b) Weight W[K,N] row-major -> B-fragment-major hi/lo (with nt offset
//     so multiple weights pack into one combined B buffer).
// ---------------------------------------------------------------------------
__global__ void __launch_bounds__(256) wfrag(const float* __restrict__ W,
                                             uint32_t* __restrict__ oh,
                                             uint32_t* __restrict__ ol,
                                             int K, int lgN, int ntOff) {
    const int id = blockIdx.x * 256 + threadIdx.x;
    const int N = 1 << lgN;
    const int p = id >> lgN;
    const int n = id & (N - 1);
    const float a = W[(size_t)(2 * p) * N + n];
    const float b = W[(size_t)(2 * p + 1) * N + n];
    const int KS = K >> 4;
    const size_t idx = ((size_t)((ntOff + (n >> 3)) * KS + (p >> 3))) * 64 +
                       ((n & 7) * 4 + (p & 3)) * 2 + ((p >> 2) & 1);
    uint32_t hi, lo;
    splitbf(a, b, hi, lo);
    oh[idx] = hi; ol[idx] = lo;
}

// ---------------------------------------------------------------------------
// 2) bf16x3 GEMM: C[M,N] = A @ B, 128x128 tile, BK=32, 3-stage cp.async.
// ---------------------------------------------------------------------------
__global__ void __launch_bounds__(256) gemm_bf3(const uint32_t* __restrict__ Ah,
                                                const uint32_t* __restrict__ Al,
                                                const uint32_t* __restrict__ Bh,
                                                const uint32_t* __restrict__ Bl,
                                                float* __restrict__ C,
                                                int N, int K) {
    extern __shared__ uint32_t sm[];
    const int tid = threadIdx.x, wid = tid >> 5, lane = tid & 31;
    const int wr = wid >> 2, wc = wid & 3, g = lane >> 2, tq = lane & 3;
    const int bm = blockIdx.y * 128, bn = blockIdx.x * 128;
    const int KS = K >> 4, NSTG = K >> 5;
    const uint32_t sbase = smem_u32(sm);

    const uint32_t* Ah0 = Ah + (size_t)(bm >> 4) * KS * 128;
    const uint32_t* Al0 = Al + (size_t)(bm >> 4) * KS * 128;
    const uint32_t* Bh0 = Bh + (size_t)(bn >> 3) * KS * 64;
    const uint32_t* Bl0 = Bl + (size_t)(bn >> 3) * KS * 64;

    float acc[4][4][4];
#pragma unroll
    for (int i = 0; i < 4; i++)
#pragma unroll
        for (int j = 0; j < 4; j++)
#pragma unroll
            for (int e = 0; e < 4; e++) acc[i][j][e] = 0.f;

#define G_ISSUE(S, BUF) do {                                                        \
    const uint32_t sb_ = sbase + (uint32_t)(BUF) * 32768u;                          \
    _Pragma("unroll")                                                               \
    for (int i_ = 0; i_ < 2; i_++) {                                                \
        const int f_ = tid + i_ * 256;                                              \
        const int mt_ = f_ >> 6, wA_ = (4 * f_) & 255;                              \
        const int ksA_ = wA_ >> 7, frA_ = wA_ & 127;                                \
        const size_t oa_ = ((size_t)mt_ * KS + (S) * 2 + ksA_) * 128 + frA_;        \
        cpa16(sb_ + f_ * 16u,           Ah0 + oa_);                                 \
        cpa16(sb_ + 8192u + f_ * 16u,   Al0 + oa_);                                 \
        const int nt_ = f_ >> 5, wB_ = (4 * f_) & 127;                              \
        const int ksB_ = wB_ >> 6, frB_ = wB_ & 63;                                 \
        const size_t ob_ = ((size_t)nt_ * KS + (S) * 2 + ksB_) * 64 + frB_;         \
        cpa16(sb_ + 16384u + f_ * 16u,  Bh0 + ob_);                                 \
        cpa16(sb_ + 24576u + f_ * 16u,  Bl0 + ob_);                                 \
    }                                                                               \
    cp_commit();                                                                    \
} while (0)

    G_ISSUE(0, 0);
    G_ISSUE(1, 1);
    for (int s = 0; s < NSTG; s++) {
        if (s + 2 < NSTG) { G_ISSUE(s + 2, (s + 2) % 3); cp_wait<2>(); }
        else if (s + 1 < NSTG) { cp_wait<1>(); }
        else { cp_wait<0>(); }
        __syncthreads();
        const uint32_t* S0 = sm + (s % 3) * 8192;
#pragma unroll
        for (int ksl = 0; ksl < 2; ksl++) {
            uint4 ah[4], al[4];
            uint2 bh[4], bl[4];
#pragma unroll
            for (int i = 0; i < 4; i++) {
                const int mt = wr * 4 + i;
                ah[i] = *(const uint4*)(S0 + (mt * 2 + ksl) * 128 + (g * 4 + tq) * 4);
                al[i] = *(const uint4*)(S0 + 2048 + (mt * 2 + ksl) * 128 + (g * 4 + tq) * 4);
            }
#pragma unroll
            for (int j = 0; j < 4; j++) {
                const int nt = wc * 4 + j;
                bh[j] = *(const uint2*)(S0 + 4096 + (nt * 2 + ksl) * 64 + (g * 4 + tq) * 2);
                bl[j] = *(const uint2*)(S0 + 6144 + (nt * 2 + ksl) * 64 + (g * 4 + tq) * 2);
            }
#pragma unroll
            for (int i = 0; i < 4; i++)
#pragma unroll
                for (int j = 0; j < 4; j++) {
                    mma_bf(acc[i][j], (const uint32_t*)&ah[i], (const uint32_t*)&bh[j]);
                    mma_bf(acc[i][j], (const uint32_t*)&ah[i], (const uint32_t*)&bl[j]);
                    mma_bf(acc[i][j], (const uint32_t*)&al[i], (const uint32_t*)&bh[j]);
                }
        }
        __syncthreads();
    }
#undef G_ISSUE

    // epilogue: row-major C
#pragma unroll
    for (int i = 0; i < 4; i++) {
        const int r0 = bm + (wr * 4 + i) * 16 + g;
#pragma unroll
        for (int j = 0; j < 4; j++) {
            const int c0 = bn + (wc * 4 + j) * 8 + 2 * tq;
            *(float2*)(C + (size_t)r0 * N + c0)       = make_float2(acc[i][j][0], acc[i][j][1]);
            *(float2*)(C + (size_t)(r0 + 8) * N + c0) = make_float2(acc[i][j][2], acc[i][j][3]);
        }
    }
}

// ---------------------------------------------------------------------------
// 3) RMSNorm + head-split: Q -> A-frags; K, V -> B-frags (hi/lo).
//    qkv row layout: [q(1024) | k(1024) | v(1024)] per token.
// ---------------------------------------------------------------------------
__global__ void __launch_bounds__(256) rms_kernel(const float* __restrict__ qkv,
                                                  const float* __restrict__ qg,
                                                  const float* __restrict__ kg,
                                                  uint32_t* __restrict__ qfh, uint32_t* __restrict__ qfl,
                                                  uint32_t* __restrict__ kfh, uint32_t* __restrict__ kfl,
                                                  uint32_t* __restrict__ vfh, uint32_t* __restrict__ vfl) {
    const int tk0 = blockIdx.x * 2;
    const int warp = threadIdx.x >> 5, lane = threadIdx.x & 31;
    const int b = tk0 >> 11, s0 = tk0 & 2047;
    const int ks = lane >> 3, c = lane & 7, tq = c & 3, ch = c >> 2;
#pragma unroll
    for (int i = 0; i < 2; i++) {
        const int h = warp * 2 + i;
        const int bh = b * 16 + h;
        const float2 gq = *(const float2*)(qg + h * 64 + 2 * lane);
        const float2 gk = *(const float2*)(kg + h * 64 + 2 * lane);
#pragma unroll
        for (int tt = 0; tt < 2; tt++) {
            const int token = tk0 + tt, s = s0 + tt;
            // q
            {
                const float2 qv = *(const float2*)(qkv + (size_t)token * 3072 + h * 64 + 2 * lane);
                float ss = qv.x * qv.x + qv.y * qv.y;
#pragma unroll
                for (int off = 16; off; off >>= 1) ss += __shfl_xor_sync(0xffffffffu, ss, off);
                const float r = rsqrtf(ss * (1.0f / DHd) + 1e-8f) * 8.0f;
                const int mt = s >> 4, mr = s & 15, gg = mr & 7, hih = mr >> 3;
                const size_t qi = ((size_t)(bh * 128 + mt) * 4 + ks) * 128 + (gg * 4 + tq) * 4 + hih + 2 * ch;
                uint32_t hi, lo;
                splitbf(qv.x * r * gq.x, qv.y * r * gq.y, hi, lo);
                qfh[qi] = hi; qfl[qi] = lo;
            }
            // k
            {
                const float2 kvv = *(const float2*)(qkv + (size_t)token * 3072 + 1024 + h * 64 + 2 * lane);
                float ss = kvv.x * kvv.x + kvv.y * kvv.y;
#pragma unroll
                for (int off = 16; off; off >>= 1) ss += __shfl_xor_sync(0xffffffffu, ss, off);
                const float r = rsqrtf(ss * (1.0f / DHd) + 1e-8f) * 8.0f;
                const int nt = s >> 3, gg = s & 7;
                const size_t ki = ((size_t)(bh * 256 + nt) * 4 + ks) * 64 + (gg * 4 + tq) * 2 + ch;
                uint32_t hi, lo;
                splitbf(kvv.x * r * gk.x, kvv.y * r * gk.y, hi, lo);
                kfh[ki] = hi; kfl[ki] = lo;
            }
        }
        // v (pairs along seq: tokens tk0, tk0+1)
        {
            const float2 va = *(const float2*)(qkv + (size_t)tk0 * 3072 + 2048 + h * 64 + 2 * lane);
            const float2 vb = *(const float2*)(qkv + (size_t)(tk0 + 1) * 3072 + 2048 + h * 64 + 2 * lane);
            const int pq = s0 >> 1;
            const int ksv = pq >> 3, cv = pq & 7, tv = cv & 3, rv = cv >> 2;
            const int d0 = 2 * lane;
            const size_t vi0 = ((size_t)(bh * 128 + ksv) * 8 + (d0 >> 3)) * 64 + ((d0 & 7) * 4 + tv) * 2 + rv;
            const size_t vi1 = ((size_t)(bh * 128 + ksv) * 8 + ((d0 + 1) >> 3)) * 64 + (((d0 + 1) & 7) * 4 + tv) * 2 + rv;
            uint32_t hi, lo;
            splitbf(va.x, vb.x, hi, lo); vfh[vi0] = hi; vfl[vi0] = lo;
            splitbf(va.y, vb.y, hi, lo); vfh[vi1] = hi; vfl[vi1] = lo;
        }
    }
}

// ---------------------------------------------------------------------------
// 4) Flash attention, bf16x3 MMA, 3-stage cp.async K/V pipeline.
// ---------------------------------------------------------------------------
__global__ void __launch_bounds__(256) attn_bf(const uint32_t* __restrict__ Qh,
                                               const uint32_t* __restrict__ Ql,
                                               const uint32_t* __restrict__ Kh,
                                               const uint32_t* __restrict__ Kl,
                                               const uint32_t* __restrict__ Vh,
                                               const uint32_t* __restrict__ Vl,
                                               uint32_t* __restrict__ Oh,
                                               uint32_t* __restrict__ Ol) {
    extern __shared__ uint32_t sm[];
    const int tid = threadIdx.x, warp = tid >> 5, lane = tid & 31;
    const int g = lane >> 2, tq = lane & 3;
    const int bh = blockIdx.y, h = bh & 15;
    const int q0 = blockIdx.x * 128;
    const uint32_t sbase = smem_u32(sm);

    // Q fragments (resident)
    uint4 qh_[4], ql_[4];
    {
        const size_t qb = ((size_t)(bh * 128 + (q0 >> 4) + warp)) * 4;
#pragma unroll
        for (int ks = 0; ks < 4; ks++) {
            qh_[ks] = *(const uint4*)(Qh + (qb + ks) * 128 + (g * 4 + tq) * 4);
            ql_[ks] = *(const uint4*)(Ql + (qb + ks) * 128 + (g * 4 + tq) * 4);
        }
    }

    const uint32_t* Kh0 = Kh + (size_t)bh * 65536;
    const uint32_t* Kl0 = Kl + (size_t)bh * 65536;
    const uint32_t* Vh0 = Vh + (size_t)bh * 65536;
    const uint32_t* Vl0 = Vl + (size_t)bh * 65536;

    float oacc[8][4];
#pragma unroll
    for (int j = 0; j < 8; j++)
#pragma unroll
        for (int e = 0; e < 4; e++) oacc[j][e] = 0.f;
    float m0 = -1e30f, m1 = -1e30f, l0 = 0.f, l1 = 0.f;

#define A_ISSUE(T, BUF) do {                                                  \
    const uint32_t sb_ = sbase + (uint32_t)(BUF) * 32768u;                    \
    _Pragma("unroll")                                                         \
    for (int i_ = 0; i_ < 2; i_++) {                                          \
        const int f_ = tid + i_ * 256;                                        \
        const size_t o_ = (size_t)(T) * 2048 + 4 * f_;                        \
        cpa16(sb_ + f_ * 16u,          Kh0 + o_);                             \
        cpa16(sb_ + 8192u + f_ * 16u,  Kl0 + o_);                             \
        cpa16(sb_ + 16384u + f_ * 16u, Vh0 + o_);                             \
        cpa16(sb_ + 24576u + f_ * 16u, Vl0 + o_);                             \
    }                                                                         \
    cp_commit();                                                              \
} while (0)

    A_ISSUE(0, 0);
    A_ISSUE(1, 1);
    const int NT = Sq / 64;
    for (int t = 0; t < NT; t++) {
        if (t + 2 < NT) { A_ISSUE(t + 2, (t + 2) % 3); cp_wait<2>(); }
        else if (t + 1 < NT) { cp_wait<1>(); }
        else { cp_wait<0>(); }
        __syncthreads();
        const uint32_t* SKh = sm + (t % 3) * 8192;
        const uint32_t* SKl = SKh + 2048;
        const uint32_t* SVh = SKh + 4096;
        const uint32_t* SVl = SKh + 6144;

        // S = Q K^T
        float sacc[8][4];
#pragma unroll
        for (int j = 0; j < 8; j++)
#pragma unroll
            for (int e = 0; e < 4; e++) sacc[j][e] = 0.f;
#pragma unroll
        for (int ks = 0; ks < 4; ks++) {
#pragma unroll
            for (int j = 0; j < 8; j++) {
                const uint2 kbh = *(const uint2*)(SKh + (j * 4 + ks) * 64 + (g * 4 + tq) * 2);
                const uint2 kbl = *(const uint2*)(SKl + (j * 4 + ks) * 64 + (g * 4 + tq) * 2);
                mma_bf(sacc[j], (const uint32_t*)&qh_[ks], (const uint32_t*)&kbh);
                mma_bf(sacc[j], (const uint32_t*)&qh_[ks], (const uint32_t*)&kbl);
                mma_bf(sacc[j], (const uint32_t*)&ql_[ks], (const uint32_t*)&kbh);
            }
        }

        // online softmax (rows g and g+8; quad lanes share a row)
        float mx0 = -1e30f, mx1 = -1e30f;
#pragma unroll
        for (int j = 0; j < 8; j++) {
            mx0 = fmaxf(mx0, fmaxf(sacc[j][0], sacc[j][1]));
            mx1 = fmaxf(mx1, fmaxf(sacc[j][2], sacc[j][3]));
        }
        mx0 = fmaxf(mx0, __shfl_xor_sync(0xffffffffu, mx0, 1));
        mx0 = fmaxf(mx0, __shfl_xor_sync(0xffffffffu, mx0, 2));
        mx1 = fmaxf(mx1, __shfl_xor_sync(0xffffffffu, mx1, 1));
        mx1 = fmaxf(mx1, __shfl_xor_sync(0xffffffffu, mx1, 2));
        const float nm0 = fmaxf(m0, mx0), nm1 = fmaxf(m1, mx1);
        const float c0 = __expf(m0 - nm0), c1 = __expf(m1 - nm1);
        float ls0 = 0.f, ls1 = 0.f;
#pragma unroll
        for (int j = 0; j < 8; j++) {
            sacc[j][0] = __expf(sacc[j][0] - nm0);
            sacc[j][1] = __expf(sacc[j][1] - nm0);
            sacc[j][2] = __expf(sacc[j][2] - nm1);
            sacc[j][3] = __expf(sacc[j][3] - nm1);
            ls0 += sacc[j][0] + sacc[j][1];
            ls1 += sacc[j][2] + sacc[j][3];
        }
        ls0 += __shfl_xor_sync(0xffffffffu, ls0, 1);
        ls0 += __shfl_xor_sync(0xffffffffu, ls0, 2);
        ls1 += __shfl_xor_sync(0xffffffffu, ls1, 1);
        ls1 += __shfl_xor_sync(0xffffffffu, ls1, 2);
        l0 = l0 * c0 + ls0; l1 = l1 * c1 + ls1;
        m0 = nm0; m1 = nm1;
#pragma unroll
        for (int j = 0; j < 8; j++) {
            oacc[j][0] *= c0; oacc[j][1] *= c0;
            oacc[j][2] *= c1; oacc[j][3] *= c1;
        }

        // P -> A-fragments (register-only)
        uint32_t pah[4][4], pal[4][4];
#pragma unroll
        for (int k2 = 0; k2 < 4; k2++) {
            splitbf(sacc[2 * k2][0],     sacc[2 * k2][1],     pah[k2][0], pal[k2][0]);
            splitbf(sacc[2 * k2][2],     sacc[2 * k2][3],     pah[k2][1], pal[k2][1]);
            splitbf(sacc[2 * k2 + 1][0], sacc[2 * k2 + 1][1], pah[k2][2], pal[k2][2]);
            splitbf(sacc[2 * k2 + 1][2], sacc[2 * k2 + 1][3], pah[k2][3], pal[k2][3]);
        }

        // O += P V
#pragma unroll
        for (int ks = 0; ks < 4; ks++) {
#pragma unroll
            for (int j = 0; j < 8; j++) {
                const uint2 vbh = *(const uint2*)(SVh + (ks * 8 + j) * 64 + (g * 4 + tq) * 2);
                const uint2 vbl = *(const uint2*)(SVl + (ks * 8 + j) * 64 + (g * 4 + tq) * 2);
                mma_bf(oacc[j], pah[ks], (const uint32_t*)&vbh);
                mma_bf(oacc[j], pah[ks], (const uint32_t*)&vbl);
                mma_bf(oacc[j], pal[ks], (const uint32_t*)&vbh);
            }
        }
        __syncthreads();
    }
#undef A_ISSUE

    // epilogue: O /= l, write A-fragment-major for output GEMM (K=INNER)
    const float inv0 = 1.0f / l0, inv1 = 1.0f / l1;
    const int mt_o = (bh >> 4) * 128 + (q0 >> 4) + warp;
#pragma unroll
    for (int j = 0; j < 8; j++) {
        const size_t ix0 = ((size_t)(mt_o * 64 + h * 4 + (j >> 1))) * 128 + (g * 4 + tq) * 4 + 2 * (j & 1);
        uint32_t hi, lo;
        splitbf(oacc[j][0] * inv0, oacc[j][1] * inv0, hi, lo);
        Oh[ix0] = hi; Ol[ix0] = lo;
        splitbf(oacc[j][2] * inv1, oacc[j][3] * inv1, hi, lo);
        Oh[ix0 + 1] = hi; Ol[ix0 + 1] = lo;
    }
}

// ---------------------------------------------------------------------------
// Launcher
// ---------------------------------------------------------------------------
#define SMEM_96K 98304

extern "C" void kernel_launch(void* const* d_in, const int* in_sizes, int n_in,
                              void* d_out, int out_size) {
    const float* x    = (const float*)d_in[0];
    const float* ln_w = (const float*)d_in[1];
    const float* ln_b = (const float*)d_in[2];
    const float* Wq   = (const float*)d_in[3];
    const float* Wkv  = (const float*)d_in[4];
    const float* qg   = (const float*)d_in[5];
    const float* kg   = (const float*)d_in[6];
    const float* Wo   = (const float*)d_in[7];
    float* out = (float*)d_out;

    uint32_t *xnh, *xnl, *wqkvh, *wqkvl, *woh, *wol;
    uint32_t *qfh, *qfl, *kfh, *kfl, *vfh, *vfl, *aoh, *aol;
    float *qkv;
    cudaGetSymbolAddress((void**)&xnh,   g_xn_h);   cudaGetSymbolAddress((void**)&xnl,   g_xn_l);
    cudaGetSymbolAddress((void**)&wqkvh, g_Wqkv_h); cudaGetSymbolAddress((void**)&wqkvl, g_Wqkv_l);
    cudaGetSymbolAddress((void**)&woh,   g_Wo_h);   cudaGetSymbolAddress((void**)&wol,   g_Wo_l);
    cudaGetSymbolAddress((void**)&qfh,   g_qf_h);   cudaGetSymbolAddress((void**)&qfl,   g_qf_l);
    cudaGetSymbolAddress((void**)&kfh,   g_kf_h);   cudaGetSymbolAddress((void**)&kfl,   g_kf_l);
    cudaGetSymbolAddress((void**)&vfh,   g_vf_h);   cudaGetSymbolAddress((void**)&vfl,   g_vf_l);
    cudaGetSymbolAddress((void**)&aoh,   g_ao_h);   cudaGetSymbolAddress((void**)&aol,   g_ao_l);
    cudaGetSymbolAddress((void**)&qkv,   g_qkv);

    cudaFuncSetAttribute(gemm_bf3, cudaFuncAttributeMaxDynamicSharedMemorySize, SMEM_96K);
    cudaFuncSetAttribute(attn_bf,  cudaFuncAttributeMaxDynamicSharedMemorySize, SMEM_96K);

    ln_kernel<<<TOK, 256>>>(x, ln_w, ln_b, xnh, xnl);
    // combined B buffer: Wq at nt 0..127, Wkv at nt 128..383
    wfrag<<<(DIM / 2) * INNER / 256, 256>>>(Wq, wqkvh, wqkvl, DIM, 10, 0);
    wfrag<<<(DIM / 2) * (2 * INNER) / 256, 256>>>(Wkv, wqkvh, wqkvl, DIM, 11, 128);
    wfrag<<<(INNER / 2) * DIM / 256, 256>>>(Wo, woh, wol, INNER, 10, 0);

    // fused QKV projection: N = 3072
    gemm_bf3<<<dim3(3 * INNER / 128, TOK / 128), 256, SMEM_96K>>>(xnh, xnl, wqkvh, wqkvl, qkv, 3 * INNER, DIM);

    rms_kernel<<<TOK / 2, 256>>>(qkv, qg, kg, qfh, qfl, kfh, kfl, vfh, vfl);

    attn_bf<<<dim3(Sq / 128, Bz * Hn), 256, SMEM_96K>>>(qfh, qfl, kfh, kfl, vfh, vfl, aoh, aol);

    gemm_bf3<<<dim3(DIM / 128, TOK / 128), 256, SMEM_96K>>>(aoh, aol, woh, wol, out, DIM, INNER);
}